// round 10
// baseline (speedup 1.0000x reference)
#include <cuda_runtime.h>
#include <math.h>

#define BB 4
#define NN 4096
#define KK 20
#define NPTS (BB*NN)            // 16384
#define EDG  (NPTS*KK)          // 327680
#define STATS_BLOCKS 512
#define FULLM 0xffffffffu

#define FINF __int_as_float(0x7f800000)
#define ULLMAX 0xFFFFFFFFFFFFFFFFULL

// ---------------- scratch (device globals; no allocations allowed) ----------
__device__ float g_dist[(size_t)BB * NN * NN];      // float distances (layer 1)
__device__ float4 g_x4[NPTS];                        // packed (x,y,z,|x|^2)
__device__ float g_d2[NPTS];
__device__ int   g_idx[NPTS * KK];
__device__ float g_u[NPTS * 256];
__device__ float g_v[NPTS * 256];
__device__ float g_vmax[NPTS * 256];
__device__ float g_vmin[NPTS * 256];
__device__ float g_h0[NPTS * 64];
__device__ float g_h1[NPTS * 256];
__device__ float g_Wd0[3 * 64];
__device__ float g_Wd1[64 * 256];
__device__ float g_part[STATS_BLOCKS * 2 * 256];
__device__ float g_scale[256];
__device__ float g_shift[256];
__device__ float g_gate[NPTS];
__device__ float g_alpha[NPTS];
__device__ float g_pool[32 * BB * 512];
__device__ float g_pooled[BB * 512];

static __device__ __forceinline__ float leaky(float v) { return v > 0.f ? v : 0.2f * v; }

// float -> order-preserving uint (ascending float == ascending uint)
static __device__ __forceinline__ unsigned okey(float f) {
    unsigned u = __float_as_uint(f);
    return u ^ ((unsigned)(((int)u) >> 31) | 0x80000000u);
}

// ---------------- warp bitonic sorts ------------------------------------------
template <int NR>
static __device__ __forceinline__ void wsortf(float* v, int lane) {
    const int N = NR * 32;
    #pragma unroll
    for (int k = 2; k <= N; k <<= 1) {
        #pragma unroll
        for (int j = k >> 1; j > 0; j >>= 1) {
            if (j >= 32) {
                int rj = j >> 5;
                #pragma unroll
                for (int rr = 0; rr < NR; rr++) {
                    int pr = rr ^ rj;
                    if (pr > rr) {
                        int p = rr * 32 + lane;
                        bool asc = ((p & k) == 0);
                        float a = v[rr], b = v[pr];
                        float mn = fminf(a, b), mx = fmaxf(a, b);
                        v[rr] = asc ? mn : mx;
                        v[pr] = asc ? mx : mn;
                    }
                }
            } else {
                #pragma unroll
                for (int rr = 0; rr < NR; rr++) {
                    int p = rr * 32 + lane;
                    bool asc = ((p & k) == 0);
                    bool lower = ((lane & j) == 0);
                    float o = __shfl_xor_sync(FULLM, v[rr], j);
                    bool keepmin = (asc == lower);
                    float mn = fminf(v[rr], o), mx = fmaxf(v[rr], o);
                    v[rr] = keepmin ? mn : mx;
                }
            }
        }
    }
}

template <int NR>
static __device__ __forceinline__ void wsortu64(unsigned long long* v, int lane) {
    const int N = NR * 32;
    #pragma unroll
    for (int k = 2; k <= N; k <<= 1) {
        #pragma unroll
        for (int j = k >> 1; j > 0; j >>= 1) {
            if (j >= 32) {
                int rj = j >> 5;
                #pragma unroll
                for (int rr = 0; rr < NR; rr++) {
                    int pr = rr ^ rj;
                    if (pr > rr) {
                        int p = rr * 32 + lane;
                        bool asc = ((p & k) == 0);
                        unsigned long long a = v[rr], b = v[pr];
                        unsigned long long mn = a < b ? a : b;
                        unsigned long long mx = a < b ? b : a;
                        v[rr] = asc ? mn : mx;
                        v[pr] = asc ? mx : mn;
                    }
                }
            } else {
                #pragma unroll
                for (int rr = 0; rr < NR; rr++) {
                    int p = rr * 32 + lane;
                    bool asc = ((p & k) == 0);
                    bool lower = ((lane & j) == 0);
                    unsigned long long o = __shfl_xor_sync(FULLM, v[rr], j);
                    bool keepmin = (asc == lower);
                    unsigned long long mn = v[rr] < o ? v[rr] : o;
                    unsigned long long mx = v[rr] < o ? o : v[rr];
                    v[rr] = keepmin ? mn : mx;
                }
            }
        }
    }
}

// ---------------- fallback streaming top-32 (exact, rare) --------------------
static __device__ __forceinline__ unsigned long long wmax64(unsigned long long m) {
    #pragma unroll
    for (int o = 16; o; o >>= 1) {
        unsigned long long ov = __shfl_xor_sync(FULLM, m, o);
        m = m > ov ? m : ov;
    }
    return m;
}

static __device__ __forceinline__ void winsert(unsigned long long c,
                                               unsigned long long& sc,
                                               unsigned long long& tau,
                                               int lane) {
    unsigned bal = __ballot_sync(FULLM, c < tau);
    while (bal) {
        int src = __ffs(bal) - 1;
        bal &= bal - 1;
        unsigned long long cn = __shfl_sync(FULLM, c, src);
        if (cn < tau) {
            unsigned eq = __ballot_sync(FULLM, sc == tau);
            if (lane == __ffs(eq) - 1) sc = cn;
            tau = wmax64(sc);
        }
    }
}

static __device__ __forceinline__ void wfinish(unsigned long long sc, int lane, int* out) {
    unsigned long long v1[1] = {sc};
    wsortu64<1>(v1, lane);
    if (lane < KK) out[lane] = (int)(v1[0] & 0xffffffffu);
}

// ---------------- candidate finish: compact, compose, sort, emit -------------
// priv: lane-private index slots (6 per lane); cnt: this lane's count.
// keyfn: functor idx -> float distance.
template <typename KF>
static __device__ __forceinline__ bool cand_finish(const int* privw, int cnt,
                                                   int* compw, int lane,
                                                   KF keyf, int* out) {
    unsigned ovf = __ballot_sync(FULLM, cnt > 6);
    // inclusive scan of cnt
    int inc = cnt;
    #pragma unroll
    for (int o = 1; o < 32; o <<= 1) {
        int n = __shfl_up_sync(FULLM, inc, o);
        if (lane >= o) inc += n;
    }
    int tot = __shfl_sync(FULLM, inc, 31);
    if (ovf || tot > 128) return false;
    int off = inc - cnt;
    for (int i = 0; i < cnt; i++) compw[off + i] = privw[i];
    __syncwarp();
    if (tot <= 64) {
        unsigned long long e[2];
        #pragma unroll
        for (int rr = 0; rr < 2; rr++) {
            int p = rr * 32 + lane;
            if (p < tot) {
                int j = compw[p];
                e[rr] = ((unsigned long long)okey(keyf(j)) << 32) | (unsigned)j;
            } else e[rr] = ULLMAX;
        }
        wsortu64<2>(e, lane);
        if (lane < KK) out[lane] = (int)(e[0] & 0xffffffffu);
    } else {
        unsigned long long e[4];
        #pragma unroll
        for (int rr = 0; rr < 4; rr++) {
            int p = rr * 32 + lane;
            if (p < tot) {
                int j = compw[p];
                e[rr] = ((unsigned long long)okey(keyf(j)) << 32) | (unsigned)j;
            } else e[rr] = ULLMAX;
        }
        wsortu64<4>(e, lane);
        if (lane < KK) out[lane] = (int)(e[0] & 0xffffffffu);
    }
    return true;
}

// ---------------- weight prep: Wd = Wp - Wt ---------------------------------
__global__ void prep_k(const float* __restrict__ Wt0, const float* __restrict__ Wp0,
                       const float* __restrict__ Wt1, const float* __restrict__ Wp1) {
    int i = blockIdx.x * 256 + threadIdx.x;
    if (i < 192) g_Wd0[i] = Wp0[i] - Wt0[i];
    int j = i - 192;
    if (j >= 0 && j < 16384) g_Wd1[j] = Wp1[j] - Wt1[j];
}

// ---------------- pack x + squared norm --------------------------------------
__global__ void pack3_k(const float* __restrict__ x) {
    int r = blockIdx.x * blockDim.x + threadIdx.x;
    if (r >= NPTS) return;
    float a = x[r * 3], b = x[r * 3 + 1], c = x[r * 3 + 2];
    g_x4[r] = make_float4(a, b, c, a * a + b * b + c * c);
}

__global__ void norms64_k() {
    int gt = blockIdx.x * blockDim.x + threadIdx.x;
    int r = gt >> 5, lane = gt & 31;
    if (r >= NPTS) return;
    const float* h = g_h0 + (size_t)r * 64;
    float a = h[lane], b = h[lane + 32];
    float s = a * a + b * b;
    #pragma unroll
    for (int o = 16; o; o >>= 1) s += __shfl_down_sync(FULLM, s, o);
    if (lane == 0) g_d2[r] = s;
}

// ---------------- layer0 u/v (3->64, trivial) --------------------------------
__global__ void uv0_k(const float* __restrict__ x, const float* __restrict__ Wt0) {
    int gid = blockIdx.x * 256 + threadIdx.x;   // NPTS*64 total
    int r = gid >> 6, c = gid & 63;
    float x0 = x[r * 3], x1 = x[r * 3 + 1], x2 = x[r * 3 + 2];
    g_u[gid] = x0 * Wt0[c] + x1 * Wt0[64 + c] + x2 * Wt0[128 + c];
    g_v[gid] = x0 * g_Wd0[c] + x1 * g_Wd0[64 + c] + x2 * g_Wd0[128 + c];
}

// ---------------- fused 16-row (64->256) GEMM: u1 = h0@Wt1, v1 = h0@Wd1 ------
__global__ __launch_bounds__(256) void gemm16_k(const float* __restrict__ Wt1) {
    __shared__ float hs[16 * 64];
    int r0 = blockIdx.x * 16;
    int t = threadIdx.x;
    #pragma unroll
    for (int s = 0; s < 4; s++) {
        int l = t + (s << 8);
        hs[l] = g_h0[(size_t)r0 * 64 + l];
    }
    __syncthreads();
    float au[16], av[16];
    #pragma unroll
    for (int r = 0; r < 16; r++) { au[r] = 0.f; av[r] = 0.f; }
    #pragma unroll 4
    for (int d = 0; d < 64; d++) {
        float wu = Wt1[d * 256 + t];
        float wv = g_Wd1[d * 256 + t];
        #pragma unroll
        for (int r = 0; r < 16; r++) {
            float h = hs[r * 64 + d];
            au[r] = fmaf(h, wu, au[r]);
            av[r] = fmaf(h, wv, av[r]);
        }
    }
    #pragma unroll
    for (int r = 0; r < 16; r++) {
        g_u[(size_t)(r0 + r) * 256 + t] = au[r];
        g_v[(size_t)(r0 + r) * 256 + t] = av[r];
    }
}

// ---------------- distance GEMM (layer1), triangular grid --------------------
static __device__ __forceinline__ int tri_start(int ti) {
    return ti * 64 - (ti * (ti - 1)) / 2;
}

__global__ __launch_bounds__(256) void dist_gemm_k() {
    const int b = blockIdx.y;
    int l = blockIdx.x;                    // 0..2079
    int ti = (int)((129.0f - sqrtf(129.0f * 129.0f - 8.0f * (float)l)) * 0.5f);
    if (ti > 63) ti = 63;
    while (ti < 63 && tri_start(ti + 1) <= l) ti++;
    while (ti > 0 && tri_start(ti) > l) ti--;
    int tj = ti + (l - tri_start(ti));
    const int i0 = ti * 64, j0 = tj * 64;
    __shared__ float As[64][68];   // pad 68 keeps 16B alignment -> LDS.128
    __shared__ float Bs[64][68];
    const float* hb = g_h0 + (size_t)b * NN * 64;
    int t = threadIdx.x;
    #pragma unroll
    for (int s = 0; s < 16; s++) {
        int ll = t + (s << 8);
        int r = ll >> 6, d = ll & 63;
        As[d][r] = hb[(size_t)(i0 + r) * 64 + d];
        Bs[d][r] = hb[(size_t)(j0 + r) * 64 + d];
    }
    __syncthreads();
    int tx = t & 15, ty = t >> 4;
    float acc[4][4];
    #pragma unroll
    for (int r = 0; r < 4; r++)
        #pragma unroll
        for (int c = 0; c < 4; c++) acc[r][c] = 0.f;
    #pragma unroll 8
    for (int d = 0; d < 64; d++) {
        float4 av = *(const float4*)&As[d][ty * 4];
        float4 bv = *(const float4*)&Bs[d][tx * 4];
        acc[0][0] = fmaf(av.x, bv.x, acc[0][0]); acc[0][1] = fmaf(av.x, bv.y, acc[0][1]);
        acc[0][2] = fmaf(av.x, bv.z, acc[0][2]); acc[0][3] = fmaf(av.x, bv.w, acc[0][3]);
        acc[1][0] = fmaf(av.y, bv.x, acc[1][0]); acc[1][1] = fmaf(av.y, bv.y, acc[1][1]);
        acc[1][2] = fmaf(av.y, bv.z, acc[1][2]); acc[1][3] = fmaf(av.y, bv.w, acc[1][3]);
        acc[2][0] = fmaf(av.z, bv.x, acc[2][0]); acc[2][1] = fmaf(av.z, bv.y, acc[2][1]);
        acc[2][2] = fmaf(av.z, bv.z, acc[2][2]); acc[2][3] = fmaf(av.z, bv.w, acc[2][3]);
        acc[3][0] = fmaf(av.w, bv.x, acc[3][0]); acc[3][1] = fmaf(av.w, bv.y, acc[3][1]);
        acc[3][2] = fmaf(av.w, bv.z, acc[3][2]); acc[3][3] = fmaf(av.w, bv.w, acc[3][3]);
    }
    const float* n2 = g_d2 + b * NN;
    float nj0 = n2[j0 + tx * 4 + 0], nj1 = n2[j0 + tx * 4 + 1];
    float nj2 = n2[j0 + tx * 4 + 2], nj3 = n2[j0 + tx * 4 + 3];
    float ov[4][4];
    #pragma unroll
    for (int r = 0; r < 4; r++) {
        float ni = n2[i0 + ty * 4 + r];
        ov[r][0] = ni + nj0 - 2.f * acc[r][0];
        ov[r][1] = ni + nj1 - 2.f * acc[r][1];
        ov[r][2] = ni + nj2 - 2.f * acc[r][2];
        ov[r][3] = ni + nj3 - 2.f * acc[r][3];
        *(float4*)&g_dist[((size_t)(b * NN + i0 + ty * 4 + r)) * NN + j0 + tx * 4] =
            make_float4(ov[r][0], ov[r][1], ov[r][2], ov[r][3]);
    }
    if (ti != tj) {
        __syncthreads();
        float* Ts = &As[0][0];                 // reuse [64][68]
        #pragma unroll
        for (int r = 0; r < 4; r++)
            #pragma unroll
            for (int c = 0; c < 4; c++)
                Ts[(tx * 4 + c) * 68 + (ty * 4 + r)] = ov[r][c];
        __syncthreads();
        #pragma unroll
        for (int s = 0; s < 16; s++) {
            int ll = t + (s << 8);
            int jr = ll >> 6, ic = ll & 63;
            g_dist[((size_t)(b * NN + j0 + jr)) * NN + i0 + ic] = Ts[jr * 68 + ic];
        }
    }
}

// ---------------- knn0: f32 two-pass threshold select -------------------------
__global__ __launch_bounds__(256) void knn0_k() {
    __shared__ float4 pts[1024];                // 16 KB
    __shared__ int priv[8][192];                // 6 KB (6 slots per lane)
    __shared__ int comp[8][128];                // 4 KB
    int t = threadIdx.x, w = t >> 5, lane = t & 31;
    int row = blockIdx.x * 8 + w;
    int base = row & ~(NN - 1);
    float4 me = g_x4[row];

    // pass 1: per-lane top-2 float distances
    float m0 = FINF, m1 = FINF;
    #pragma unroll 1
    for (int chunk = 0; chunk < 4; chunk++) {
        __syncthreads();
        #pragma unroll
        for (int i = 0; i < 4; i++)
            pts[t + (i << 8)] = g_x4[base + (chunk << 10) + t + (i << 8)];
        __syncthreads();
        #pragma unroll 4
        for (int it = 0; it < 32; it++) {
            float4 p = pts[(it << 5) + lane];
            float dot = me.x * p.x + me.y * p.y + me.z * p.z;
            float d = me.w + p.w - 2.f * dot;
            if (d < m0) { m1 = m0; m0 = d; }
            else if (d < m1) { m1 = d; }
        }
    }
    float v2[2] = {m0, m1};
    wsortf<2>(v2, lane);
    float tau = __shfl_sync(FULLM, v2[0], 31);   // 32nd smallest collected

    // pass 2: lane-private index push, no warp ops
    int cnt = 0;
    int* privw = &priv[w][lane * 6];
    #pragma unroll 1
    for (int chunk = 0; chunk < 4; chunk++) {
        __syncthreads();
        #pragma unroll
        for (int i = 0; i < 4; i++)
            pts[t + (i << 8)] = g_x4[base + (chunk << 10) + t + (i << 8)];
        __syncthreads();
        #pragma unroll 4
        for (int it = 0; it < 32; it++) {
            int jl = (it << 5) + lane;
            float4 p = pts[jl];
            float dot = me.x * p.x + me.y * p.y + me.z * p.z;
            float d = me.w + p.w - 2.f * dot;
            if (d <= tau) {
                if (cnt < 6) privw[cnt] = (chunk << 10) + jl;
                cnt++;
            }
        }
    }
    int* out = g_idx + row * KK;
    auto keyf = [&](int j) {
        float4 p = g_x4[base + j];
        float dot = me.x * p.x + me.y * p.y + me.z * p.z;
        return me.w + p.w - 2.f * dot;
    };
    if (!cand_finish(privw, cnt, comp[w], lane, keyf, out)) {
        // exact streaming fallback (degenerate ties)
        unsigned long long sc, tau2;
        {
            float d = keyf(lane);
            sc = ((unsigned long long)okey(d) << 32) | (unsigned)lane;
            tau2 = wmax64(sc);
        }
        for (int it = 1; it < 128; it++) {
            int j = (it << 5) + lane;
            float d = keyf(j);
            unsigned long long c = ((unsigned long long)okey(d) << 32) | (unsigned)j;
            winsert(c, sc, tau2, lane);
        }
        wfinish(sc, lane, out);
    }
}

// ---------------- knn1: f32 two-pass threshold select over dist rows ----------
__global__ __launch_bounds__(256) void knn1_k() {
    __shared__ int priv[8][192];                // 6 KB
    __shared__ int comp[8][128];                // 4 KB
    int t = threadIdx.x, w = t >> 5, lane = t & 31;
    int row = blockIdx.x * 8 + w;
    const float4* dr = (const float4*)(g_dist + (size_t)row * NN);   // 1024 float4

    // pass 1
    float m0 = FINF, m1 = FINF;
    #pragma unroll 4
    for (int it = 0; it < 32; it++) {
        float4 dv = __ldg(&dr[(it << 5) + lane]);
        if (dv.x < m0) { m1 = m0; m0 = dv.x; } else if (dv.x < m1) m1 = dv.x;
        if (dv.y < m0) { m1 = m0; m0 = dv.y; } else if (dv.y < m1) m1 = dv.y;
        if (dv.z < m0) { m1 = m0; m0 = dv.z; } else if (dv.z < m1) m1 = dv.z;
        if (dv.w < m0) { m1 = m0; m0 = dv.w; } else if (dv.w < m1) m1 = dv.w;
    }
    float v2[2] = {m0, m1};
    wsortf<2>(v2, lane);
    float tau = __shfl_sync(FULLM, v2[0], 31);

    // pass 2 (row L1-resident)
    int cnt = 0;
    int* privw = &priv[w][lane * 6];
    #pragma unroll 2
    for (int it = 0; it < 32; it++) {
        int j4 = (it << 5) + lane;
        float4 dv = __ldg(&dr[j4]);
        int jb = j4 << 2;
        if (dv.x <= tau) { if (cnt < 6) privw[cnt] = jb + 0; cnt++; }
        if (dv.y <= tau) { if (cnt < 6) privw[cnt] = jb + 1; cnt++; }
        if (dv.z <= tau) { if (cnt < 6) privw[cnt] = jb + 2; cnt++; }
        if (dv.w <= tau) { if (cnt < 6) privw[cnt] = jb + 3; cnt++; }
    }
    int* out = g_idx + row * KK;
    const float* drs = g_dist + (size_t)row * NN;
    auto keyf = [&](int j) { return __ldg(&drs[j]); };
    if (!cand_finish(privw, cnt, comp[w], lane, keyf, out)) {
        unsigned long long sc, tau2;
        {
            sc = ((unsigned long long)okey(drs[lane]) << 32) | (unsigned)lane;
            tau2 = wmax64(sc);
        }
        for (int it = 1; it < 128; it++) {
            int j = (it << 5) + lane;
            unsigned long long c = ((unsigned long long)okey(__ldg(&drs[j])) << 32) | (unsigned)j;
            winsert(c, sc, tau2, lane);
        }
        wfinish(sc, lane, out);
    }
}

// ---------------- fused gather: BN stats + per-point neighbor vmax/vmin ------
template <int C>
__global__ __launch_bounds__(256) void gather_k() {
    constexpr int G = 256 / C;
    int t = threadIdx.x;
    int c = t % C;
    int g = t / C;
    float s = 0.f, s2 = 0.f;
    for (int p = blockIdx.x * G + g; p < NPTS; p += STATS_BLOCKS * G) {
        int b = p >> 12;
        float uc = g_u[(size_t)p * C + c];
        const int* ip = g_idx + p * KK;
        float S = 0.f, Q = 0.f, mx = -FINF, mn = FINF;
        #pragma unroll
        for (int k = 0; k < KK; k++) {
            int j = ip[k];
            float v = g_v[((size_t)((b << 12) + j)) * C + c];
            S += v;
            Q = fmaf(v, v, Q);
            mx = fmaxf(mx, v);
            mn = fminf(mn, v);
        }
        g_vmax[(size_t)p * C + c] = mx;
        g_vmin[(size_t)p * C + c] = mn;
        s += fmaf(20.f, uc, S);
        s2 += fmaf(20.f * uc, uc, fmaf(2.f * uc, S, Q));
    }
    __shared__ float sh[256], sh2[256];
    sh[t] = s; sh2[t] = s2;
    __syncthreads();
    if (t < C) {
        float S = sh[t], S2 = sh2[t];
        #pragma unroll
        for (int gg = 1; gg < G; gg++) { S += sh[gg * C + t]; S2 += sh2[gg * C + t]; }
        g_part[blockIdx.x * (2 * C) + t] = S;
        g_part[blockIdx.x * (2 * C) + C + t] = S2;
    }
}

template <int C>
__global__ void fin_k(const float* __restrict__ gamma, const float* __restrict__ beta) {
    int c = threadIdx.x;
    float S = 0.f, S2 = 0.f;
    for (int bk = 0; bk < STATS_BLOCKS; bk++) {
        S += g_part[bk * 2 * C + c];
        S2 += g_part[bk * 2 * C + C + c];
    }
    const float inv = 1.f / (float)EDG;
    float mu = S * inv;
    float var = S2 * inv - mu * mu;
    float sc = gamma[c] * rsqrtf(var + 1e-5f);
    g_scale[c] = sc;
    g_shift[c] = beta[c] - mu * sc;
}

// ---------------- finish: h = leaky(scale*(u + vmax/vmin) + shift) -----------
template <int C>
__global__ void finish_k() {
    int gid = blockIdx.x * 256 + threadIdx.x;    // NPTS*C
    int c = gid & (C - 1);
    float sc = g_scale[c];
    float vm = (sc >= 0.f) ? g_vmax[gid] : g_vmin[gid];
    float M = g_u[gid] + vm;
    float* out = (C == 64) ? (float*)g_h0 : (float*)g_h1;
    out[gid] = leaky(fmaf(M, sc, g_shift[c]));
}

// ---------------- attention gate + softmax -----------------------------------
__global__ void gate_k(const float* __restrict__ Wg, const float* __restrict__ bg) {
    int gt = blockIdx.x * 256 + threadIdx.x;
    int r = gt >> 5, lane = gt & 31;
    if (r >= NPTS) return;
    const float* h = g_h1 + (size_t)r * 256;
    float s = 0.f;
    #pragma unroll
    for (int q = 0; q < 8; q++) {
        int d = lane + (q << 5);
        s = fmaf(h[d], Wg[d], s);
    }
    #pragma unroll
    for (int o = 16; o; o >>= 1) s += __shfl_down_sync(FULLM, s, o);
    if (lane == 0) {
        float gg = s + bg[0];
        g_gate[r] = gg > 0.f ? gg : 0.f;
    }
}

__global__ void softmax_k() {
    int b = blockIdx.x, t = threadIdx.x;
    __shared__ float sh[256];
    const float* gp = g_gate + (b << 12);
    float* ap = g_alpha + (b << 12);
    float mx = -FINF;
    for (int s = 0; s < 16; s++) mx = fmaxf(mx, gp[t + (s << 8)]);
    sh[t] = mx; __syncthreads();
    for (int o = 128; o; o >>= 1) { if (t < o) sh[t] = fmaxf(sh[t], sh[t + o]); __syncthreads(); }
    float M = sh[0];
    __syncthreads();
    float sum = 0.f;
    for (int s = 0; s < 16; s++) {
        int j = t + (s << 8);
        float e = expf(gp[j] - M);
        ap[j] = e;
        sum += e;
    }
    sh[t] = sum; __syncthreads();
    for (int o = 128; o; o >>= 1) { if (t < o) sh[t] += sh[t + o]; __syncthreads(); }
    float inv = 1.f / sh[0];
    for (int s = 0; s < 16; s++) ap[t + (s << 8)] *= inv;
}

// ---------------- fused feat GEMM + weighted pooling --------------------------
__global__ __launch_bounds__(256) void pool_k(const float* __restrict__ Wf,
                                              const float* __restrict__ bf) {
    int b = blockIdx.x;
    int t = threadIdx.x;
    int ch = blockIdx.y * 256 + t;
    int slab = blockIdx.z;
    __shared__ float hr[16][256];
    __shared__ float al[16];
    float acc = 0.f;
    float bfc = bf[ch];
    for (int gidx = 0; gidx < 8; gidx++) {
        int nb = (slab << 7) + (gidx << 4);
        __syncthreads();
        #pragma unroll
        for (int s = 0; s < 16; s++)
            hr[s][t] = g_h1[((size_t)(b << 12) + nb + s) * 256 + t];
        if (t < 16) al[t] = g_alpha[(b << 12) + nb + t];
        __syncthreads();
        float sacc[16];
        #pragma unroll
        for (int r = 0; r < 16; r++) sacc[r] = bfc;
        #pragma unroll 4
        for (int d = 0; d < 256; d += 4) {
            float w0 = Wf[(d + 0) * 512 + ch];
            float w1 = Wf[(d + 1) * 512 + ch];
            float w2 = Wf[(d + 2) * 512 + ch];
            float w3 = Wf[(d + 3) * 512 + ch];
            #pragma unroll
            for (int r = 0; r < 16; r++) {
                float4 hv = *(const float4*)&hr[r][d];
                sacc[r] = fmaf(hv.x, w0, fmaf(hv.y, w1, fmaf(hv.z, w2, fmaf(hv.w, w3, sacc[r]))));
            }
        }
        #pragma unroll
        for (int r = 0; r < 16; r++) {
            float f = sacc[r] > 0.f ? sacc[r] : 0.f;
            acc = fmaf(al[r], f, acc);
        }
    }
    g_pool[((slab << 2) + b) * 512 + ch] = acc;
}

__global__ void poolred_k() {
    int gid = blockIdx.x * 256 + threadIdx.x;  // BB*512
    if (gid >= BB * 512) return;
    int b = gid >> 9, ch = gid & 511;
    float s = 0.f;
    for (int sl = 0; sl < 32; sl++) s += g_pool[((sl << 2) + b) * 512 + ch];
    g_pooled[gid] = s;
}

__global__ void final_k(const float* __restrict__ Wl, const float* __restrict__ bl,
                        float* __restrict__ out) {
    int b = blockIdx.x, o = threadIdx.x;
    const float* p = g_pooled + b * 512;
    float s = bl[o];
    #pragma unroll 8
    for (int f = 0; f < 512; f++) s = fmaf(p[f], Wl[f * 256 + o], s);
    out[b * 256 + o] = s;
}

// ---------------- launch ------------------------------------------------------
extern "C" void kernel_launch(void* const* d_in, const int* in_sizes, int n_in,
                              void* d_out, int out_size) {
    (void)in_sizes; (void)n_in; (void)out_size;
    const float* x   = (const float*)d_in[0];
    const float* Wt0 = (const float*)d_in[1];
    const float* Wp0 = (const float*)d_in[3];
    const float* g0  = (const float*)d_in[5];
    const float* be0 = (const float*)d_in[6];
    const float* Wt1 = (const float*)d_in[7];
    const float* Wp1 = (const float*)d_in[9];
    const float* g1  = (const float*)d_in[11];
    const float* be1 = (const float*)d_in[12];
    const float* Wg  = (const float*)d_in[13];
    const float* bg  = (const float*)d_in[14];
    const float* Wf  = (const float*)d_in[15];
    const float* bf  = (const float*)d_in[16];
    const float* Wl  = (const float*)d_in[17];
    const float* bl  = (const float*)d_in[18];
    float* out = (float*)d_out;

    // ---- layer 0 ----
    prep_k<<<65, 256>>>(Wt0, Wp0, Wt1, Wp1);
    pack3_k<<<64, 256>>>(x);
    uv0_k<<<NPTS * 64 / 256, 256>>>(x, Wt0);
    knn0_k<<<NPTS / 8, 256>>>();
    gather_k<64><<<STATS_BLOCKS, 256>>>();
    fin_k<64><<<1, 64>>>(g0, be0);
    finish_k<64><<<NPTS * 64 / 256, 256>>>();

    // ---- layer 1 ----
    norms64_k<<<NPTS * 32 / 256, 256>>>();
    gemm16_k<<<NPTS / 16, 256>>>(Wt1);
    dist_gemm_k<<<dim3(2080, BB), 256>>>();
    knn1_k<<<NPTS / 8, 256>>>();
    gather_k<256><<<STATS_BLOCKS, 256>>>();
    fin_k<256><<<1, 256>>>(g1, be1);
    finish_k<256><<<NPTS * 256 / 256, 256>>>();

    // ---- attention pooling + final linear ----
    gate_k<<<NPTS * 32 / 256, 256>>>(Wg, bg);
    softmax_k<<<BB, 256>>>();
    pool_k<<<dim3(BB, 2, 32), 256>>>(Wf, bf);
    poolred_k<<<8, 256>>>();
    final_k<<<BB, 256>>>(Wl, bl, out);
}

// round 11
// speedup vs baseline: 1.1577x; 1.1577x over previous
#include <cuda_runtime.h>
#include <math.h>

#define BB 4
#define NN 4096
#define KK 20
#define NPTS (BB*NN)            // 16384
#define EDG  (NPTS*KK)          // 327680
#define STATS_BLOCKS 512
#define FULLM 0xffffffffu

#define FINF __int_as_float(0x7f800000)
#define ULLMAX 0xFFFFFFFFFFFFFFFFULL

// ---------------- scratch (device globals; no allocations allowed) ----------
__device__ float g_dist[(size_t)BB * NN * NN];      // float distances (layer 1)
__device__ float4 g_x4[NPTS];                        // packed (x,y,z,|x|^2)
__device__ float g_d2[NPTS];
__device__ int   g_idx[NPTS * KK];
__device__ float g_u[NPTS * 256];
__device__ float g_v[NPTS * 256];
__device__ float g_vmax[NPTS * 256];
__device__ float g_vmin[NPTS * 256];
__device__ float g_h0[NPTS * 64];
__device__ float g_h1[NPTS * 256];
__device__ float g_Wd0[3 * 64];
__device__ float g_Wd1[64 * 256];
__device__ float g_part[STATS_BLOCKS * 2 * 256];
__device__ float g_scale[256];
__device__ float g_shift[256];
__device__ float g_gate[NPTS];
__device__ float g_alpha[NPTS];
__device__ float g_pool[32 * BB * 512];
__device__ float g_pooled[BB * 512];

static __device__ __forceinline__ float leaky(float v) { return v > 0.f ? v : 0.2f * v; }

// float -> order-preserving uint (ascending float == ascending uint)
static __device__ __forceinline__ unsigned okey(float f) {
    unsigned u = __float_as_uint(f);
    return u ^ ((unsigned)(((int)u) >> 31) | 0x80000000u);
}

// ---------------- warp bitonic sorts ------------------------------------------
template <int NR>
static __device__ __forceinline__ void wsortf(float* v, int lane) {
    const int N = NR * 32;
    #pragma unroll
    for (int k = 2; k <= N; k <<= 1) {
        #pragma unroll
        for (int j = k >> 1; j > 0; j >>= 1) {
            if (j >= 32) {
                int rj = j >> 5;
                #pragma unroll
                for (int rr = 0; rr < NR; rr++) {
                    int pr = rr ^ rj;
                    if (pr > rr) {
                        int p = rr * 32 + lane;
                        bool asc = ((p & k) == 0);
                        float a = v[rr], b = v[pr];
                        float mn = fminf(a, b), mx = fmaxf(a, b);
                        v[rr] = asc ? mn : mx;
                        v[pr] = asc ? mx : mn;
                    }
                }
            } else {
                #pragma unroll
                for (int rr = 0; rr < NR; rr++) {
                    int p = rr * 32 + lane;
                    bool asc = ((p & k) == 0);
                    bool lower = ((lane & j) == 0);
                    float o = __shfl_xor_sync(FULLM, v[rr], j);
                    bool keepmin = (asc == lower);
                    float mn = fminf(v[rr], o), mx = fmaxf(v[rr], o);
                    v[rr] = keepmin ? mn : mx;
                }
            }
        }
    }
}

template <int NR>
static __device__ __forceinline__ void wsortu64(unsigned long long* v, int lane) {
    const int N = NR * 32;
    #pragma unroll
    for (int k = 2; k <= N; k <<= 1) {
        #pragma unroll
        for (int j = k >> 1; j > 0; j >>= 1) {
            if (j >= 32) {
                int rj = j >> 5;
                #pragma unroll
                for (int rr = 0; rr < NR; rr++) {
                    int pr = rr ^ rj;
                    if (pr > rr) {
                        int p = rr * 32 + lane;
                        bool asc = ((p & k) == 0);
                        unsigned long long a = v[rr], b = v[pr];
                        unsigned long long mn = a < b ? a : b;
                        unsigned long long mx = a < b ? b : a;
                        v[rr] = asc ? mn : mx;
                        v[pr] = asc ? mx : mn;
                    }
                }
            } else {
                #pragma unroll
                for (int rr = 0; rr < NR; rr++) {
                    int p = rr * 32 + lane;
                    bool asc = ((p & k) == 0);
                    bool lower = ((lane & j) == 0);
                    unsigned long long o = __shfl_xor_sync(FULLM, v[rr], j);
                    bool keepmin = (asc == lower);
                    unsigned long long mn = v[rr] < o ? v[rr] : o;
                    unsigned long long mx = v[rr] < o ? o : v[rr];
                    v[rr] = keepmin ? mn : mx;
                }
            }
        }
    }
}

// ---------------- fallback streaming top-32 (exact, rare) --------------------
static __device__ __forceinline__ unsigned long long wmax64(unsigned long long m) {
    #pragma unroll
    for (int o = 16; o; o >>= 1) {
        unsigned long long ov = __shfl_xor_sync(FULLM, m, o);
        m = m > ov ? m : ov;
    }
    return m;
}

static __device__ __forceinline__ void winsert(unsigned long long c,
                                               unsigned long long& sc,
                                               unsigned long long& tau,
                                               int lane) {
    unsigned bal = __ballot_sync(FULLM, c < tau);
    while (bal) {
        int src = __ffs(bal) - 1;
        bal &= bal - 1;
        unsigned long long cn = __shfl_sync(FULLM, c, src);
        if (cn < tau) {
            unsigned eq = __ballot_sync(FULLM, sc == tau);
            if (lane == __ffs(eq) - 1) sc = cn;
            tau = wmax64(sc);
        }
    }
}

static __device__ __forceinline__ void wfinish(unsigned long long sc, int lane, int* out) {
    unsigned long long v1[1] = {sc};
    wsortu64<1>(v1, lane);
    if (lane < KK) out[lane] = (int)(v1[0] & 0xffffffffu);
}

// sort <=128 composites already in smem buf, emit KK indices
static __device__ __forceinline__ bool buf_finish(unsigned long long* bufw, int cnt,
                                                  int lane, int* out) {
    if (cnt > 128) return false;
    if (cnt <= 64) {
        unsigned long long e[2];
        e[0] = (lane < cnt) ? bufw[lane] : ULLMAX;
        e[1] = (lane + 32 < cnt) ? bufw[lane + 32] : ULLMAX;
        wsortu64<2>(e, lane);
        if (lane < KK) out[lane] = (int)(e[0] & 0xffffffffu);
    } else {
        unsigned long long e[4];
        #pragma unroll
        for (int rr = 0; rr < 4; rr++)
            e[rr] = (rr * 32 + lane < cnt) ? bufw[rr * 32 + lane] : ULLMAX;
        wsortu64<4>(e, lane);
        if (lane < KK) out[lane] = (int)(e[0] & 0xffffffffu);
    }
    return true;
}

// ---------------- weight prep: Wd = Wp - Wt ---------------------------------
__global__ void prep_k(const float* __restrict__ Wt0, const float* __restrict__ Wp0,
                       const float* __restrict__ Wt1, const float* __restrict__ Wp1) {
    int i = blockIdx.x * 256 + threadIdx.x;
    if (i < 192) g_Wd0[i] = Wp0[i] - Wt0[i];
    int j = i - 192;
    if (j >= 0 && j < 16384) g_Wd1[j] = Wp1[j] - Wt1[j];
}

// ---------------- pack x + squared norm --------------------------------------
__global__ void pack3_k(const float* __restrict__ x) {
    int r = blockIdx.x * blockDim.x + threadIdx.x;
    if (r >= NPTS) return;
    float a = x[r * 3], b = x[r * 3 + 1], c = x[r * 3 + 2];
    g_x4[r] = make_float4(a, b, c, a * a + b * b + c * c);
}

__global__ void norms64_k() {
    int gt = blockIdx.x * blockDim.x + threadIdx.x;
    int r = gt >> 5, lane = gt & 31;
    if (r >= NPTS) return;
    const float* h = g_h0 + (size_t)r * 64;
    float a = h[lane], b = h[lane + 32];
    float s = a * a + b * b;
    #pragma unroll
    for (int o = 16; o; o >>= 1) s += __shfl_down_sync(FULLM, s, o);
    if (lane == 0) g_d2[r] = s;
}

// ---------------- layer0 u/v (3->64, trivial) --------------------------------
__global__ void uv0_k(const float* __restrict__ x, const float* __restrict__ Wt0) {
    int gid = blockIdx.x * 256 + threadIdx.x;   // NPTS*64 total
    int r = gid >> 6, c = gid & 63;
    float x0 = x[r * 3], x1 = x[r * 3 + 1], x2 = x[r * 3 + 2];
    g_u[gid] = x0 * Wt0[c] + x1 * Wt0[64 + c] + x2 * Wt0[128 + c];
    g_v[gid] = x0 * g_Wd0[c] + x1 * g_Wd0[64 + c] + x2 * g_Wd0[128 + c];
}

// ---------------- fused 16-row (64->256) GEMM: u1 = h0@Wt1, v1 = h0@Wd1 ------
__global__ __launch_bounds__(256) void gemm16_k(const float* __restrict__ Wt1) {
    __shared__ float hs[16 * 64];
    int r0 = blockIdx.x * 16;
    int t = threadIdx.x;
    #pragma unroll
    for (int s = 0; s < 4; s++) {
        int l = t + (s << 8);
        hs[l] = g_h0[(size_t)r0 * 64 + l];
    }
    __syncthreads();
    float au[16], av[16];
    #pragma unroll
    for (int r = 0; r < 16; r++) { au[r] = 0.f; av[r] = 0.f; }
    #pragma unroll 4
    for (int d = 0; d < 64; d++) {
        float wu = Wt1[d * 256 + t];
        float wv = g_Wd1[d * 256 + t];
        #pragma unroll
        for (int r = 0; r < 16; r++) {
            float h = hs[r * 64 + d];
            au[r] = fmaf(h, wu, au[r]);
            av[r] = fmaf(h, wv, av[r]);
        }
    }
    #pragma unroll
    for (int r = 0; r < 16; r++) {
        g_u[(size_t)(r0 + r) * 256 + t] = au[r];
        g_v[(size_t)(r0 + r) * 256 + t] = av[r];
    }
}

// ---------------- distance GEMM (layer1), triangular grid --------------------
static __device__ __forceinline__ int tri_start(int ti) {
    return ti * 64 - (ti * (ti - 1)) / 2;
}

__global__ __launch_bounds__(256) void dist_gemm_k() {
    const int b = blockIdx.y;
    int l = blockIdx.x;                    // 0..2079
    int ti = (int)((129.0f - sqrtf(129.0f * 129.0f - 8.0f * (float)l)) * 0.5f);
    if (ti > 63) ti = 63;
    while (ti < 63 && tri_start(ti + 1) <= l) ti++;
    while (ti > 0 && tri_start(ti) > l) ti--;
    int tj = ti + (l - tri_start(ti));
    const int i0 = ti * 64, j0 = tj * 64;
    __shared__ float As[64][65];
    __shared__ float Bs[64][65];
    const float* hb = g_h0 + (size_t)b * NN * 64;
    int t = threadIdx.x;
    #pragma unroll
    for (int s = 0; s < 16; s++) {
        int ll = t + (s << 8);
        int r = ll >> 6, d = ll & 63;
        As[d][r] = hb[(size_t)(i0 + r) * 64 + d];
        Bs[d][r] = hb[(size_t)(j0 + r) * 64 + d];
    }
    __syncthreads();
    int tx = t & 15, ty = t >> 4;
    float acc[4][4];
    #pragma unroll
    for (int r = 0; r < 4; r++)
        #pragma unroll
        for (int c = 0; c < 4; c++) acc[r][c] = 0.f;
    #pragma unroll 8
    for (int d = 0; d < 64; d++) {
        float a0 = As[d][ty * 4 + 0], a1 = As[d][ty * 4 + 1];
        float a2 = As[d][ty * 4 + 2], a3 = As[d][ty * 4 + 3];
        float b0 = Bs[d][tx * 4 + 0], b1 = Bs[d][tx * 4 + 1];
        float b2 = Bs[d][tx * 4 + 2], b3 = Bs[d][tx * 4 + 3];
        acc[0][0] = fmaf(a0, b0, acc[0][0]); acc[0][1] = fmaf(a0, b1, acc[0][1]);
        acc[0][2] = fmaf(a0, b2, acc[0][2]); acc[0][3] = fmaf(a0, b3, acc[0][3]);
        acc[1][0] = fmaf(a1, b0, acc[1][0]); acc[1][1] = fmaf(a1, b1, acc[1][1]);
        acc[1][2] = fmaf(a1, b2, acc[1][2]); acc[1][3] = fmaf(a1, b3, acc[1][3]);
        acc[2][0] = fmaf(a2, b0, acc[2][0]); acc[2][1] = fmaf(a2, b1, acc[2][1]);
        acc[2][2] = fmaf(a2, b2, acc[2][2]); acc[2][3] = fmaf(a2, b3, acc[2][3]);
        acc[3][0] = fmaf(a3, b0, acc[3][0]); acc[3][1] = fmaf(a3, b1, acc[3][1]);
        acc[3][2] = fmaf(a3, b2, acc[3][2]); acc[3][3] = fmaf(a3, b3, acc[3][3]);
    }
    const float* n2 = g_d2 + b * NN;
    float nj0 = n2[j0 + tx * 4 + 0], nj1 = n2[j0 + tx * 4 + 1];
    float nj2 = n2[j0 + tx * 4 + 2], nj3 = n2[j0 + tx * 4 + 3];
    float ov[4][4];
    #pragma unroll
    for (int r = 0; r < 4; r++) {
        float ni = n2[i0 + ty * 4 + r];
        ov[r][0] = ni + nj0 - 2.f * acc[r][0];
        ov[r][1] = ni + nj1 - 2.f * acc[r][1];
        ov[r][2] = ni + nj2 - 2.f * acc[r][2];
        ov[r][3] = ni + nj3 - 2.f * acc[r][3];
        *(float4*)&g_dist[((size_t)(b * NN + i0 + ty * 4 + r)) * NN + j0 + tx * 4] =
            make_float4(ov[r][0], ov[r][1], ov[r][2], ov[r][3]);
    }
    if (ti != tj) {
        __syncthreads();
        float* Ts = &As[0][0];                 // reuse [64][65]
        #pragma unroll
        for (int r = 0; r < 4; r++)
            #pragma unroll
            for (int c = 0; c < 4; c++)
                Ts[(tx * 4 + c) * 65 + (ty * 4 + r)] = ov[r][c];
        __syncthreads();
        #pragma unroll
        for (int s = 0; s < 16; s++) {
            int ll = t + (s << 8);
            int jr = ll >> 6, ic = ll & 63;
            g_dist[((size_t)(b * NN + j0 + jr)) * NN + i0 + ic] = Ts[jr * 65 + ic];
        }
    }
}

// ---------------- knn0: f32 pass1 + ballot-compact pass2 ---------------------
__global__ __launch_bounds__(256) void knn0_k() {
    __shared__ float4 pts[1024];                    // 16 KB
    __shared__ unsigned long long buf[8][128];      // 8 KB
    int t = threadIdx.x, w = t >> 5, lane = t & 31;
    int row = blockIdx.x * 8 + w;
    int base = row & ~(NN - 1);
    float4 me = g_x4[row];

    // pass 1: per-lane top-2 float distances (fma pipe)
    float m0 = FINF, m1 = FINF;
    #pragma unroll 1
    for (int chunk = 0; chunk < 4; chunk++) {
        __syncthreads();
        #pragma unroll
        for (int i = 0; i < 4; i++)
            pts[t + (i << 8)] = g_x4[base + (chunk << 10) + t + (i << 8)];
        __syncthreads();
        #pragma unroll 4
        for (int it = 0; it < 32; it++) {
            float4 p = pts[(it << 5) + lane];
            float dot = me.x * p.x + me.y * p.y + me.z * p.z;
            float d = me.w + p.w - 2.f * dot;
            if (d < m0) { m1 = m0; m0 = d; }
            else if (d < m1) { m1 = d; }
        }
    }
    float v2[2] = {m0, m1};
    wsortf<2>(v2, lane);
    float tau = __shfl_sync(FULLM, v2[0], 31);   // 32nd smallest collected

    // pass 2: ballot-compact composites of all d <= tau
    int cnt = 0;
    #pragma unroll 1
    for (int chunk = 0; chunk < 4; chunk++) {
        __syncthreads();
        #pragma unroll
        for (int i = 0; i < 4; i++)
            pts[t + (i << 8)] = g_x4[base + (chunk << 10) + t + (i << 8)];
        __syncthreads();
        #pragma unroll 4
        for (int it = 0; it < 32; it++) {
            int jl = (it << 5) + lane;
            float4 p = pts[jl];
            float dot = me.x * p.x + me.y * p.y + me.z * p.z;
            float d = me.w + p.w - 2.f * dot;
            unsigned mask = __ballot_sync(FULLM, d <= tau);
            if (d <= tau) {
                int pos = cnt + __popc(mask & ((1u << lane) - 1));
                if (pos < 128)
                    buf[w][pos] = ((unsigned long long)okey(d) << 32)
                                | (unsigned)((chunk << 10) + jl);
            }
            cnt += __popc(mask);
        }
    }
    int* out = g_idx + row * KK;
    if (!buf_finish(buf[w], cnt, lane, out)) {
        // exact streaming fallback (degenerate ties)
        unsigned long long sc, tau2;
        {
            float4 p = g_x4[base + lane];
            float dot = me.x * p.x + me.y * p.y + me.z * p.z;
            float d = me.w + p.w - 2.f * dot;
            sc = ((unsigned long long)okey(d) << 32) | (unsigned)lane;
            tau2 = wmax64(sc);
        }
        for (int it = 1; it < 128; it++) {
            int j = (it << 5) + lane;
            float4 p = g_x4[base + j];
            float dot = me.x * p.x + me.y * p.y + me.z * p.z;
            float d = me.w + p.w - 2.f * dot;
            unsigned long long c = ((unsigned long long)okey(d) << 32) | (unsigned)j;
            winsert(c, sc, tau2, lane);
        }
        wfinish(sc, lane, out);
    }
}

// ---------------- knn1: f32 pass1 + ballot-compact pass2 over dist rows ------
__global__ __launch_bounds__(256) void knn1_k() {
    __shared__ unsigned long long buf[8][128];      // 8 KB
    int t = threadIdx.x, w = t >> 5, lane = t & 31;
    int row = blockIdx.x * 8 + w;
    const float4* dr = (const float4*)(g_dist + (size_t)row * NN);   // 1024 float4

    // pass 1
    float m0 = FINF, m1 = FINF;
    #pragma unroll 4
    for (int it = 0; it < 32; it++) {
        float4 dv = __ldg(&dr[(it << 5) + lane]);
        if (dv.x < m0) { m1 = m0; m0 = dv.x; } else if (dv.x < m1) m1 = dv.x;
        if (dv.y < m0) { m1 = m0; m0 = dv.y; } else if (dv.y < m1) m1 = dv.y;
        if (dv.z < m0) { m1 = m0; m0 = dv.z; } else if (dv.z < m1) m1 = dv.z;
        if (dv.w < m0) { m1 = m0; m0 = dv.w; } else if (dv.w < m1) m1 = dv.w;
    }
    float v2[2] = {m0, m1};
    wsortf<2>(v2, lane);
    float tau = __shfl_sync(FULLM, v2[0], 31);

    // pass 2 (row L1-resident)
    int cnt = 0;
    #pragma unroll 2
    for (int it = 0; it < 32; it++) {
        int j4 = (it << 5) + lane;
        float4 dv = __ldg(&dr[j4]);
        int jb = j4 << 2;
        float ds[4] = {dv.x, dv.y, dv.z, dv.w};
        #pragma unroll
        for (int q = 0; q < 4; q++) {
            float d = ds[q];
            unsigned mask = __ballot_sync(FULLM, d <= tau);
            if (d <= tau) {
                int pos = cnt + __popc(mask & ((1u << lane) - 1));
                if (pos < 128)
                    buf[w][pos] = ((unsigned long long)okey(d) << 32) | (unsigned)(jb + q);
            }
            cnt += __popc(mask);
        }
    }
    int* out = g_idx + row * KK;
    if (!buf_finish(buf[w], cnt, lane, out)) {
        const float* drs = g_dist + (size_t)row * NN;
        unsigned long long sc, tau2;
        {
            sc = ((unsigned long long)okey(drs[lane]) << 32) | (unsigned)lane;
            tau2 = wmax64(sc);
        }
        for (int it = 1; it < 128; it++) {
            int j = (it << 5) + lane;
            unsigned long long c = ((unsigned long long)okey(__ldg(&drs[j])) << 32) | (unsigned)j;
            winsert(c, sc, tau2, lane);
        }
        wfinish(sc, lane, out);
    }
}

// ---------------- fused gather: BN stats + per-point neighbor vmax/vmin ------
template <int C>
__global__ __launch_bounds__(256) void gather_k() {
    constexpr int G = 256 / C;
    int t = threadIdx.x;
    int c = t % C;
    int g = t / C;
    float s = 0.f, s2 = 0.f;
    for (int p = blockIdx.x * G + g; p < NPTS; p += STATS_BLOCKS * G) {
        int b = p >> 12;
        float uc = g_u[(size_t)p * C + c];
        const int* ip = g_idx + p * KK;
        float S = 0.f, Q = 0.f, mx = -FINF, mn = FINF;
        #pragma unroll
        for (int k = 0; k < KK; k++) {
            int j = ip[k];
            float v = g_v[((size_t)((b << 12) + j)) * C + c];
            S += v;
            Q = fmaf(v, v, Q);
            mx = fmaxf(mx, v);
            mn = fminf(mn, v);
        }
        g_vmax[(size_t)p * C + c] = mx;
        g_vmin[(size_t)p * C + c] = mn;
        s += fmaf(20.f, uc, S);
        s2 += fmaf(20.f * uc, uc, fmaf(2.f * uc, S, Q));
    }
    __shared__ float sh[256], sh2[256];
    sh[t] = s; sh2[t] = s2;
    __syncthreads();
    if (t < C) {
        float S = sh[t], S2 = sh2[t];
        #pragma unroll
        for (int gg = 1; gg < G; gg++) { S += sh[gg * C + t]; S2 += sh2[gg * C + t]; }
        g_part[blockIdx.x * (2 * C) + t] = S;
        g_part[blockIdx.x * (2 * C) + C + t] = S2;
    }
}

template <int C>
__global__ void fin_k(const float* __restrict__ gamma, const float* __restrict__ beta) {
    int c = threadIdx.x;
    float S = 0.f, S2 = 0.f;
    for (int bk = 0; bk < STATS_BLOCKS; bk++) {
        S += g_part[bk * 2 * C + c];
        S2 += g_part[bk * 2 * C + C + c];
    }
    const float inv = 1.f / (float)EDG;
    float mu = S * inv;
    float var = S2 * inv - mu * mu;
    float sc = gamma[c] * rsqrtf(var + 1e-5f);
    g_scale[c] = sc;
    g_shift[c] = beta[c] - mu * sc;
}

// ---------------- finish: h = leaky(scale*(u + vmax/vmin) + shift) -----------
template <int C>
__global__ void finish_k() {
    int gid = blockIdx.x * 256 + threadIdx.x;    // NPTS*C
    int c = gid & (C - 1);
    float sc = g_scale[c];
    float vm = (sc >= 0.f) ? g_vmax[gid] : g_vmin[gid];
    float M = g_u[gid] + vm;
    float* out = (C == 64) ? (float*)g_h0 : (float*)g_h1;
    out[gid] = leaky(fmaf(M, sc, g_shift[c]));
}

// ---------------- attention gate + softmax -----------------------------------
__global__ void gate_k(const float* __restrict__ Wg, const float* __restrict__ bg) {
    int gt = blockIdx.x * 256 + threadIdx.x;
    int r = gt >> 5, lane = gt & 31;
    if (r >= NPTS) return;
    const float* h = g_h1 + (size_t)r * 256;
    float s = 0.f;
    #pragma unroll
    for (int q = 0; q < 8; q++) {
        int d = lane + (q << 5);
        s = fmaf(h[d], Wg[d], s);
    }
    #pragma unroll
    for (int o = 16; o; o >>= 1) s += __shfl_down_sync(FULLM, s, o);
    if (lane == 0) {
        float gg = s + bg[0];
        g_gate[r] = gg > 0.f ? gg : 0.f;
    }
}

__global__ void softmax_k() {
    int b = blockIdx.x, t = threadIdx.x;
    __shared__ float sh[256];
    const float* gp = g_gate + (b << 12);
    float* ap = g_alpha + (b << 12);
    float mx = -FINF;
    for (int s = 0; s < 16; s++) mx = fmaxf(mx, gp[t + (s << 8)]);
    sh[t] = mx; __syncthreads();
    for (int o = 128; o; o >>= 1) { if (t < o) sh[t] = fmaxf(sh[t], sh[t + o]); __syncthreads(); }
    float M = sh[0];
    __syncthreads();
    float sum = 0.f;
    for (int s = 0; s < 16; s++) {
        int j = t + (s << 8);
        float e = expf(gp[j] - M);
        ap[j] = e;
        sum += e;
    }
    sh[t] = sum; __syncthreads();
    for (int o = 128; o; o >>= 1) { if (t < o) sh[t] += sh[t + o]; __syncthreads(); }
    float inv = 1.f / sh[0];
    for (int s = 0; s < 16; s++) ap[t + (s << 8)] *= inv;
}

// ---------------- fused feat GEMM + weighted pooling --------------------------
__global__ __launch_bounds__(256) void pool_k(const float* __restrict__ Wf,
                                              const float* __restrict__ bf) {
    int b = blockIdx.x;
    int t = threadIdx.x;
    int ch = blockIdx.y * 256 + t;
    int slab = blockIdx.z;
    __shared__ float hr[16][256];
    __shared__ float al[16];
    float acc = 0.f;
    float bfc = bf[ch];
    for (int gidx = 0; gidx < 8; gidx++) {
        int nb = (slab << 7) + (gidx << 4);
        __syncthreads();
        #pragma unroll
        for (int s = 0; s < 16; s++)
            hr[s][t] = g_h1[((size_t)(b << 12) + nb + s) * 256 + t];
        if (t < 16) al[t] = g_alpha[(b << 12) + nb + t];
        __syncthreads();
        float sacc[16];
        #pragma unroll
        for (int r = 0; r < 16; r++) sacc[r] = bfc;
        #pragma unroll 4
        for (int d = 0; d < 256; d += 4) {
            float w0 = Wf[(d + 0) * 512 + ch];
            float w1 = Wf[(d + 1) * 512 + ch];
            float w2 = Wf[(d + 2) * 512 + ch];
            float w3 = Wf[(d + 3) * 512 + ch];
            #pragma unroll
            for (int r = 0; r < 16; r++) {
                float4 hv = *(const float4*)&hr[r][d];
                sacc[r] = fmaf(hv.x, w0, fmaf(hv.y, w1, fmaf(hv.z, w2, fmaf(hv.w, w3, sacc[r]))));
            }
        }
        #pragma unroll
        for (int r = 0; r < 16; r++) {
            float f = sacc[r] > 0.f ? sacc[r] : 0.f;
            acc = fmaf(al[r], f, acc);
        }
    }
    g_pool[((slab << 2) + b) * 512 + ch] = acc;
}

__global__ void poolred_k() {
    int gid = blockIdx.x * 256 + threadIdx.x;  // BB*512
    if (gid >= BB * 512) return;
    int b = gid >> 9, ch = gid & 511;
    float s = 0.f;
    for (int sl = 0; sl < 32; sl++) s += g_pool[((sl << 2) + b) * 512 + ch];
    g_pooled[gid] = s;
}

__global__ void final_k(const float* __restrict__ Wl, const float* __restrict__ bl,
                        float* __restrict__ out) {
    int b = blockIdx.x, o = threadIdx.x;
    const float* p = g_pooled + b * 512;
    float s = bl[o];
    #pragma unroll 8
    for (int f = 0; f < 512; f++) s = fmaf(p[f], Wl[f * 256 + o], s);
    out[b * 256 + o] = s;
}

// ---------------- launch ------------------------------------------------------
extern "C" void kernel_launch(void* const* d_in, const int* in_sizes, int n_in,
                              void* d_out, int out_size) {
    (void)in_sizes; (void)n_in; (void)out_size;
    const float* x   = (const float*)d_in[0];
    const float* Wt0 = (const float*)d_in[1];
    const float* Wp0 = (const float*)d_in[3];
    const float* g0  = (const float*)d_in[5];
    const float* be0 = (const float*)d_in[6];
    const float* Wt1 = (const float*)d_in[7];
    const float* Wp1 = (const float*)d_in[9];
    const float* g1  = (const float*)d_in[11];
    const float* be1 = (const float*)d_in[12];
    const float* Wg  = (const float*)d_in[13];
    const float* bg  = (const float*)d_in[14];
    const float* Wf  = (const float*)d_in[15];
    const float* bf  = (const float*)d_in[16];
    const float* Wl  = (const float*)d_in[17];
    const float* bl  = (const float*)d_in[18];
    float* out = (float*)d_out;

    // ---- layer 0 ----
    prep_k<<<65, 256>>>(Wt0, Wp0, Wt1, Wp1);
    pack3_k<<<64, 256>>>(x);
    uv0_k<<<NPTS * 64 / 256, 256>>>(x, Wt0);
    knn0_k<<<NPTS / 8, 256>>>();
    gather_k<64><<<STATS_BLOCKS, 256>>>();
    fin_k<64><<<1, 64>>>(g0, be0);
    finish_k<64><<<NPTS * 64 / 256, 256>>>();

    // ---- layer 1 ----
    norms64_k<<<NPTS * 32 / 256, 256>>>();
    gemm16_k<<<NPTS / 16, 256>>>(Wt1);
    dist_gemm_k<<<dim3(2080, BB), 256>>>();
    knn1_k<<<NPTS / 8, 256>>>();
    gather_k<256><<<STATS_BLOCKS, 256>>>();
    fin_k<256><<<1, 256>>>(g1, be1);
    finish_k<256><<<NPTS * 256 / 256, 256>>>();

    // ---- attention pooling + final linear ----
    gate_k<<<NPTS * 32 / 256, 256>>>(Wg, bg);
    softmax_k<<<BB, 256>>>();
    pool_k<<<dim3(BB, 2, 32), 256>>>(Wf, bf);
    poolred_k<<<8, 256>>>();
    final_k<<<BB, 256>>>(Wl, bl, out);
}